// round 2
// baseline (speedup 1.0000x reference)
#include <cuda_runtime.h>

#define BB   32
#define NN   512
#define DD   256
#define HH   8
#define HDIM 32
#define EE   16384
#define ETOT (EE + NN)

// ---------------- scratch (static device globals; no allocation) -------------
__device__ float g_xw [BB * NN * DD];
__device__ float g_Q  [BB * NN * DD];
__device__ float g_K  [BB * NN * DD];
__device__ float g_V  [BB * NN * DD];
__device__ float g_att[BB * NN * DD];
__device__ int   g_deg[NN];
__device__ int   g_rowptr[NN + 1];
__device__ int   g_cnt[NN];
__device__ int   g_src [ETOT];
__device__ float g_norm[ETOT];
__device__ int   g_e64;      // 1 if edge buffer is int64-layout, 0 if int32

// ---------------- edge dtype detection ---------------------------------------
// If the buffer really holds int64 values < 2^31 (little-endian), every odd
// int32 word is zero. Random int32 values in [0,512) make all-64-zero odds
// essentially impossible.
__global__ void k_detect(const int* __restrict__ e) {
    int nz = 0;
    for (int i = 0; i < 64; i++) nz += (e[2 * i + 1] != 0);
    g_e64 = (nz == 0) ? 1 : 0;
}

__device__ __forceinline__ int edge_at(const int* __restrict__ e, int idx) {
    return g_e64 ? e[2 * idx] : e[idx];
}

// ---------------- graph prep -------------------------------------------------
__global__ void k_init() {
    int t = threadIdx.x;
    if (t < NN) { g_deg[t] = 0; g_cnt[t] = 0; }
}

__global__ void k_deg(const int* __restrict__ edge) {
    int e = blockIdx.x * blockDim.x + threadIdx.x;
    if (e >= ETOT) return;
    int dst = (e < EE) ? edge_at(edge, EE + e) : (e - EE);
    if (dst < 0 || dst >= NN) return;   // defensive
    atomicAdd(&g_deg[dst], 1);
}

__global__ void k_scan() {
    __shared__ int s[NN];
    int t = threadIdx.x;
    s[t] = g_deg[t];
    __syncthreads();
    for (int off = 1; off < NN; off <<= 1) {
        int v = (t >= off) ? s[t - off] : 0;
        __syncthreads();
        s[t] += v;
        __syncthreads();
    }
    g_rowptr[t + 1] = s[t];
    if (t == 0) g_rowptr[0] = 0;
}

__global__ void k_fill(const int* __restrict__ edge) {
    int e = blockIdx.x * blockDim.x + threadIdx.x;
    if (e >= ETOT) return;
    int s, d;
    if (e < EE) { s = edge_at(edge, e); d = edge_at(edge, EE + e); }
    else        { s = e - EE; d = e - EE; }
    if (s < 0 || s >= NN || d < 0 || d >= NN) return;   // defensive
    float nm = rsqrtf((float)g_deg[s]) * rsqrtf((float)g_deg[d]);
    int pos = g_rowptr[d] + atomicAdd(&g_cnt[d], 1);
    g_src[pos]  = s;
    g_norm[pos] = nm;
}

// ---------------- dense GEMM: C[M=16384,256] = A[M,256] @ W[256,256] (+bias) --
// 128x128 tile, BK=8, 256 threads, 8x8 microtile per thread.
__global__ __launch_bounds__(256) void k_gemm(const float* __restrict__ A,
                                              const float* __restrict__ W,
                                              const float* __restrict__ bias,
                                              float* __restrict__ C) {
    const int BM = 128, BN = 128, BK = 8;
    __shared__ float As[BK * BM];
    __shared__ float Bs[BK * BN];
    int tid  = threadIdx.x;
    int cCol = blockIdx.x;   // 0..1
    int cRow = blockIdx.y;   // 0..127

    const float* Ab = A + (size_t)cRow * BM * 256;
    const float* Bb = W + cCol * BN;

    int aRow = tid >> 1;            // 0..127
    int aCol = (tid & 1) * 4;       // 0 or 4
    int bRow = tid >> 5;            // 0..7
    int bCol = (tid & 31) * 4;      // 0..124
    int tr   = tid >> 4;            // 0..15
    int tc   = tid & 15;            // 0..15

    float acc[8][8];
    #pragma unroll
    for (int i = 0; i < 8; i++)
        #pragma unroll
        for (int j = 0; j < 8; j++) acc[i][j] = 0.f;

    for (int k0 = 0; k0 < 256; k0 += BK) {
        float4 a4 = *(const float4*)(Ab + (size_t)aRow * 256 + k0 + aCol);
        As[(aCol + 0) * BM + aRow] = a4.x;
        As[(aCol + 1) * BM + aRow] = a4.y;
        As[(aCol + 2) * BM + aRow] = a4.z;
        As[(aCol + 3) * BM + aRow] = a4.w;
        *(float4*)(Bs + bRow * BN + bCol) =
            *(const float4*)(Bb + (size_t)(k0 + bRow) * 256 + bCol);
        __syncthreads();
        #pragma unroll
        for (int k = 0; k < BK; k++) {
            float rm[8], rn[8];
            *(float4*)(rm)     = *(float4*)(As + k * BM + tr * 8);
            *(float4*)(rm + 4) = *(float4*)(As + k * BM + tr * 8 + 4);
            *(float4*)(rn)     = *(float4*)(Bs + k * BN + tc * 8);
            *(float4*)(rn + 4) = *(float4*)(Bs + k * BN + tc * 8 + 4);
            #pragma unroll
            for (int i = 0; i < 8; i++)
                #pragma unroll
                for (int j = 0; j < 8; j++)
                    acc[i][j] += rm[i] * rn[j];
        }
        __syncthreads();
    }

    float bv[8];
    #pragma unroll
    for (int j = 0; j < 8; j++)
        bv[j] = bias ? bias[cCol * 128 + tc * 8 + j] : 0.f;

    #pragma unroll
    for (int i = 0; i < 8; i++) {
        size_t row = (size_t)cRow * 128 + tr * 8 + i;
        float* Cr = C + row * 256 + cCol * 128 + tc * 8;
        float4 v0, v1;
        v0.x = acc[i][0] + bv[0]; v0.y = acc[i][1] + bv[1];
        v0.z = acc[i][2] + bv[2]; v0.w = acc[i][3] + bv[3];
        v1.x = acc[i][4] + bv[4]; v1.y = acc[i][5] + bv[5];
        v1.z = acc[i][6] + bv[6]; v1.w = acc[i][7] + bv[7];
        *(float4*)(Cr)     = v0;
        *(float4*)(Cr + 4) = v1;
    }
}

// ---------------- GCN aggregation (gather over CSR-by-dst) -------------------
__global__ void k_agg(const float* __restrict__ xw,
                      const float* __restrict__ bias,
                      float* __restrict__ out) {
    int n = blockIdx.x;
    int b = blockIdx.y;
    int d = threadIdx.x;   // 0..255
    int s0 = g_rowptr[n], s1 = g_rowptr[n + 1];
    const float* base = xw + (size_t)b * NN * DD;
    float acc = bias[d];
    for (int i = s0; i < s1; i++) {
        int   s  = g_src[i];
        float nm = g_norm[i];
        acc += nm * base[(size_t)s * DD + d];
    }
    out[((size_t)b * NN + n) * DD + d] = acc;
}

// ---------------- masked attention (full-row softmax, smem energy tile) ------
#define QT 64
#define KC 64
#define SMEM_ATTN ((QT * NN + QT * 33 + KC * 33 + QT) * 4)

__global__ __launch_bounds__(256) void k_attn(const float* __restrict__ Q,
                                              const float* __restrict__ K,
                                              const float* __restrict__ V,
                                              const int* __restrict__ mask,
                                              float* __restrict__ out) {
    extern __shared__ float sm[];
    float* Et   = sm;                    // QT x NN unnormalized probs / energies
    float* Qs   = Et + QT * NN;          // QT x 33
    float* Ks   = Qs + QT * 33;          // KC x 33 (reused as Vs)
    float* lsum = Ks + KC * 33;          // QT

    int q0 = blockIdx.x * QT;
    int h  = blockIdx.y;
    int b  = blockIdx.z;
    int tid = threadIdx.x;

    const float* Qb = Q + ((size_t)b * NN + q0) * DD + h * HDIM;
    const float* Kb = K + (size_t)b * NN * DD + h * HDIM;
    const float* Vb = V + (size_t)b * NN * DD + h * HDIM;

    const float escale = 0.17677669529663687f;  // 1/sqrt(HD)

    // load Q tile (pre-scaled)
    for (int idx = tid; idx < QT * HDIM; idx += 256) {
        int r = idx >> 5, d = idx & 31;
        Qs[r * 33 + d] = Qb[(size_t)r * DD + d] * escale;
    }

    int tr = tid >> 4, tc = tid & 15;

    // phase 1: energies + mask -> Et
    for (int c = 0; c < NN; c += KC) {
        __syncthreads();   // Qs ready / Ks safe to overwrite
        for (int idx = tid; idx < KC * HDIM; idx += 256) {
            int r = idx >> 5, d = idx & 31;
            Ks[r * 33 + d] = Kb[(size_t)(c + r) * DD + d];
        }
        __syncthreads();
        float acc[4][4];
        #pragma unroll
        for (int i = 0; i < 4; i++)
            #pragma unroll
            for (int j = 0; j < 4; j++) acc[i][j] = 0.f;
        #pragma unroll
        for (int d = 0; d < HDIM; d++) {
            float qr[4], kr[4];
            #pragma unroll
            for (int i = 0; i < 4; i++) qr[i] = Qs[(tr * 4 + i) * 33 + d];
            #pragma unroll
            for (int j = 0; j < 4; j++) kr[j] = Ks[(tc * 4 + j) * 33 + d];
            #pragma unroll
            for (int i = 0; i < 4; i++)
                #pragma unroll
                for (int j = 0; j < 4; j++)
                    acc[i][j] += qr[i] * kr[j];
        }
        #pragma unroll
        for (int i = 0; i < 4; i++) {
            int qg = q0 + tr * 4 + i;
            int kg = c + tc * 4;
            int4 m4 = *(const int4*)(mask + (size_t)qg * NN + kg);
            float4 ev;
            ev.x = m4.x ? acc[i][0] : -1e10f;
            ev.y = m4.y ? acc[i][1] : -1e10f;
            ev.z = m4.z ? acc[i][2] : -1e10f;
            ev.w = m4.w ? acc[i][3] : -1e10f;
            *(float4*)(Et + (tr * 4 + i) * NN + kg) = ev;
        }
    }
    __syncthreads();

    // phase 2: row softmax (unnormalized p + row sum)
    int w = tid >> 5, lane = tid & 31;
    for (int r8 = 0; r8 < 8; r8++) {
        int r = w * 8 + r8;
        float* row = Et + r * NN;
        float m = -3.4e38f;
        #pragma unroll
        for (int t = 0; t < 16; t++) m = fmaxf(m, row[lane + 32 * t]);
        #pragma unroll
        for (int o = 16; o; o >>= 1) m = fmaxf(m, __shfl_xor_sync(0xffffffffu, m, o));
        float s = 0.f;
        #pragma unroll
        for (int t = 0; t < 16; t++) {
            float p = __expf(row[lane + 32 * t] - m);
            row[lane + 32 * t] = p;
            s += p;
        }
        #pragma unroll
        for (int o = 16; o; o >>= 1) s += __shfl_xor_sync(0xffffffffu, s, o);
        if (lane == 0) lsum[r] = s;
    }

    // phase 3: AV
    float oacc[8];
    #pragma unroll
    for (int q = 0; q < 8; q++) oacc[q] = 0.f;
    float* Vs = Ks;
    for (int c = 0; c < NN; c += KC) {
        __syncthreads();
        for (int idx = tid; idx < KC * HDIM; idx += 256) {
            int r = idx >> 5, d = idx & 31;
            Vs[r * 33 + d] = Vb[(size_t)(c + r) * DD + d];
        }
        __syncthreads();
        #pragma unroll 4
        for (int k = 0; k < KC; k++) {
            float v = Vs[k * 33 + lane];
            #pragma unroll
            for (int q = 0; q < 8; q++)
                oacc[q] += Et[(w * 8 + q) * NN + c + k] * v;
        }
    }

    #pragma unroll
    for (int q = 0; q < 8; q++) {
        int r = w * 8 + q;
        out[((size_t)b * NN + q0 + r) * DD + h * HDIM + lane] = oacc[q] / lsum[r];
    }
}

// ---------------- launch ------------------------------------------------------
extern "C" void kernel_launch(void* const* d_in, const int* in_sizes, int n_in,
                              void* d_out, int out_size) {
    const float* query = (const float*)d_in[0];
    const float* key   = (const float*)d_in[1];
    const float* value = (const float*)d_in[2];
    const int*   edge  = (const int*)d_in[3];
    const int*   mask  = (const int*)d_in[4];
    const float* Wq = (const float*)d_in[5];
    const float* bq = (const float*)d_in[6];
    const float* Wk = (const float*)d_in[7];
    const float* bk = (const float*)d_in[8];
    const float* Wv = (const float*)d_in[9];
    const float* bv = (const float*)d_in[10];
    const float* Wo = (const float*)d_in[11];
    const float* bo = (const float*)d_in[12];
    float* out = (float*)d_out;

    float *xw, *Qp, *Kp, *Vp, *att;
    cudaGetSymbolAddress((void**)&xw,  g_xw);
    cudaGetSymbolAddress((void**)&Qp,  g_Q);
    cudaGetSymbolAddress((void**)&Kp,  g_K);
    cudaGetSymbolAddress((void**)&Vp,  g_V);
    cudaGetSymbolAddress((void**)&att, g_att);

    cudaFuncSetAttribute(k_attn, cudaFuncAttributeMaxDynamicSharedMemorySize,
                         SMEM_ATTN);

    // graph prep
    k_detect<<<1, 1>>>(edge);
    k_init<<<1, NN>>>();
    k_deg <<<(ETOT + 255) / 256, 256>>>(edge);
    k_scan<<<1, NN>>>();
    k_fill<<<(ETOT + 255) / 256, 256>>>(edge);

    dim3 ggrid(2, 128);                 // N=256 / 128, M=16384 / 128
    dim3 agrid(NN, BB);
    dim3 tgrid(NN / QT, HH, BB);

    // Q/K/V: GEMM then GCN aggregation (bias added post-aggregation)
    k_gemm<<<ggrid, 256>>>(query, Wq, nullptr, xw);
    k_agg <<<agrid, 256>>>(xw, bq, Qp);
    k_gemm<<<ggrid, 256>>>(key,   Wk, nullptr, xw);
    k_agg <<<agrid, 256>>>(xw, bk, Kp);
    k_gemm<<<ggrid, 256>>>(value, Wv, nullptr, xw);
    k_agg <<<agrid, 256>>>(xw, bv, Vp);

    // masked multi-head attention
    k_attn<<<tgrid, 256, SMEM_ATTN>>>(Qp, Kp, Vp, mask, att);

    // output projection (+bias) straight into d_out
    k_gemm<<<ggrid, 256>>>(att, Wo, bo, out);
}